// round 2
// baseline (speedup 1.0000x reference)
#include <cuda_runtime.h>
#include <cuda_bf16.h>
#include <math.h>

#define N_USERS   50000
#define N_ENT     100000
#define N_NODES   150000
#define N_EDGES   3000000
#define BATCH     8192
#define OUT_COLS  176
#define LEAKY     0.2f

// ---------------- scratch (device globals; no allocation allowed) ------------
__device__ float4 g_egoA4[N_NODES * 16];   // up to 64 floats/row
__device__ float4 g_egoB4[N_NODES * 16];
__device__ float4 g_side4[N_NODES * 16];
__device__ float4 g_all4 [N_NODES * 44];   // 176 floats/row

// ---------------- init: concat embeddings -> egoA and all_emb[:,0:64] --------
__global__ void init_kernel(const float4* __restrict__ u4,
                            const float4* __restrict__ e4) {
    int gid = blockIdx.x * blockDim.x + threadIdx.x;
    if (gid >= N_NODES * 16) return;
    int r = gid >> 4;
    int c = gid & 15;
    float4 v = (r < N_USERS) ? u4[gid] : e4[gid - N_USERS * 16];
    g_egoA4[gid] = v;
    g_all4[r * 44 + c] = v;
}

// ---------------- edge phase: side[h] += A * ego[t], vectorized red ----------
template <int CH>  // CH = din/4 float4 chunks per row (power of 2)
__global__ void edge_kernel(const int*   __restrict__ all_h,
                            const int*   __restrict__ all_t,
                            const float* __restrict__ A,
                            const float4* __restrict__ ego4,
                            float4* __restrict__ side4) {
    int gid = blockIdx.x * blockDim.x + threadIdx.x;
    if (gid >= N_EDGES * CH) return;
    int e = gid >> (CH == 16 ? 4 : 3);
    int c = gid & (CH - 1);
    int t = all_t[e];
    int h = all_h[e];
    float a = A[e];
    float4 v = ego4[t * CH + c];
    float4* p = side4 + h * CH + c;
    asm volatile("red.global.add.v4.f32 [%0], {%1,%2,%3,%4};"
                 :: "l"(p), "f"(a * v.x), "f"(a * v.y), "f"(a * v.z), "f"(a * v.w)
                 : "memory");
}

// ---------------- node phase: two GEMMs + leaky + norm -----------------------
// Block = 256 threads = 4 row-groups of 64 threads; grid-stride over rows.
template <int DIN, int DOUT>
__global__ void node_kernel(const float* __restrict__ ego_in,
                            const float* __restrict__ side,
                            float* __restrict__ ego_out,
                            const float* __restrict__ Wg,
                            const float* __restrict__ bg,
                            const float* __restrict__ Wb,
                            const float* __restrict__ bb,
                            float* __restrict__ all_emb,
                            int col_off) {
    __shared__ float sWg[DIN * DOUT];
    __shared__ float sWb[DIN * DOUT];
    __shared__ float sbg[DOUT];
    __shared__ float sbb[DOUT];
    __shared__ float sxs[4][DIN];
    __shared__ float sxb[4][DIN];
    __shared__ float swsum[4][2];

    int tid = threadIdx.x;
    for (int i = tid; i < DIN * DOUT; i += 256) { sWg[i] = Wg[i]; sWb[i] = Wb[i]; }
    if (tid < DOUT) { sbg[tid] = bg[tid]; sbb[tid] = bb[tid]; }
    __syncthreads();

    int g    = tid >> 6;          // row-group 0..3
    int j    = tid & 63;          // column / lane-in-group
    int wing = j >> 5;            // warp within group (0/1)
    int lane = tid & 31;

    for (int base = blockIdx.x * 4; base < N_NODES; base += gridDim.x * 4) {
        int row = base + g;
        bool active = row < N_NODES;

        if (active) {
            for (int i = j; i < DIN; i += 64) {
                float e = ego_in[row * DIN + i];
                float s = side  [row * DIN + i];
                sxs[g][i] = e + s;
                sxb[g][i] = e * s;
            }
        }
        __syncthreads();

        float out = 0.f;
        if (active && j < DOUT) {
            float sg = sbg[j], bi = sbb[j];
            #pragma unroll
            for (int i = 0; i < DIN; i++) {
                sg += sxs[g][i] * sWg[i * DOUT + j];
                bi += sxb[g][i] * sWb[i * DOUT + j];
            }
            sg = sg > 0.f ? sg : LEAKY * sg;
            bi = bi > 0.f ? bi : LEAKY * bi;
            out = sg + bi;
        }

        // L2 norm over the DOUT outputs of this row (2-warp reduce)
        float p = out * out;
        #pragma unroll
        for (int o = 16; o > 0; o >>= 1) p += __shfl_xor_sync(0xffffffffu, p, o);
        if (lane == 0) swsum[g][wing] = p;
        __syncthreads();

        if (active && j < DOUT) {
            float tot = swsum[g][0] + swsum[g][1];
            float r = sqrtf(tot);
            float nv = out / fmaxf(r, 1e-12f);
            ego_out[row * DOUT + j] = out;                    // un-normalized carries forward
            all_emb[row * OUT_COLS + col_off + j] = nv;       // normalized goes to concat
        }
        __syncthreads();  // protect sxs/swsum reuse next iteration
    }
}

// ---------------- final gather: (u_e, pos_i_e, neg_i_e) ----------------------
__global__ void gather_kernel(const int* __restrict__ users,
                              const int* __restrict__ pos,
                              const int* __restrict__ neg,
                              float4* __restrict__ out4) {
    int gid = blockIdx.x * blockDim.x + threadIdx.x;
    if (gid >= 3 * BATCH * 44) return;
    int idx   = gid / 44;
    int c     = gid - idx * 44;
    int which = idx / BATCH;
    int b     = idx - which * BATCH;
    int row = (which == 0) ? users[b]
            : (which == 1) ? (N_USERS + pos[b])
                           : (N_USERS + neg[b]);
    out4[gid] = g_all4[row * 44 + c];
}

// -----------------------------------------------------------------------------
extern "C" void kernel_launch(void* const* d_in, const int* in_sizes, int n_in,
                              void* d_out, int out_size) {
    const int*   users = (const int*)  d_in[0];
    const int*   pos   = (const int*)  d_in[1];
    const int*   neg   = (const int*)  d_in[2];
    const int*   all_h = (const int*)  d_in[3];
    const int*   all_t = (const int*)  d_in[4];
    const float* Aval  = (const float*)d_in[5];
    const float* u_emb = (const float*)d_in[6];
    const float* e_emb = (const float*)d_in[7];
    const float* Wg0 = (const float*)d_in[8];
    const float* bg0 = (const float*)d_in[9];
    const float* Wb0 = (const float*)d_in[10];
    const float* bb0 = (const float*)d_in[11];
    const float* Wg1 = (const float*)d_in[12];
    const float* bg1 = (const float*)d_in[13];
    const float* Wb1 = (const float*)d_in[14];
    const float* bb1 = (const float*)d_in[15];
    const float* Wg2 = (const float*)d_in[16];
    const float* bg2 = (const float*)d_in[17];
    const float* Wb2 = (const float*)d_in[18];
    const float* bb2 = (const float*)d_in[19];

    void *pA, *pB, *pS, *pAll;
    cudaGetSymbolAddress(&pA,   g_egoA4);
    cudaGetSymbolAddress(&pB,   g_egoB4);
    cudaGetSymbolAddress(&pS,   g_side4);
    cudaGetSymbolAddress(&pAll, g_all4);
    float* egoA = (float*)pA;
    float* egoB = (float*)pB;
    float* side = (float*)pS;
    float* all  = (float*)pAll;

    const int TB = 256;
    const int NODE_GRID = 148 * 6;

    // init: ego0 + all_emb[:,0:64]
    init_kernel<<<(N_NODES * 16 + TB - 1) / TB, TB>>>(
        (const float4*)u_emb, (const float4*)e_emb);

    // ---- layer 0: 64 -> 64 (egoA -> egoB), norm to cols [64,128) ----
    cudaMemsetAsync(side, 0, (size_t)N_NODES * 64 * sizeof(float));
    edge_kernel<16><<<(N_EDGES * 16 + TB - 1) / TB, TB>>>(
        all_h, all_t, Aval, (const float4*)egoA, (float4*)side);
    node_kernel<64, 64><<<NODE_GRID, TB>>>(
        egoA, side, egoB, Wg0, bg0, Wb0, bb0, all, 64);

    // ---- layer 1: 64 -> 32 (egoB -> egoA), norm to cols [128,160) ----
    cudaMemsetAsync(side, 0, (size_t)N_NODES * 64 * sizeof(float));
    edge_kernel<16><<<(N_EDGES * 16 + TB - 1) / TB, TB>>>(
        all_h, all_t, Aval, (const float4*)egoB, (float4*)side);
    node_kernel<64, 32><<<NODE_GRID, TB>>>(
        egoB, side, egoA, Wg1, bg1, Wb1, bb1, all, 128);

    // ---- layer 2: 32 -> 16 (egoA -> egoB), norm to cols [160,176) ----
    cudaMemsetAsync(side, 0, (size_t)N_NODES * 32 * sizeof(float));
    edge_kernel<8><<<(N_EDGES * 8 + TB - 1) / TB, TB>>>(
        all_h, all_t, Aval, (const float4*)egoA, (float4*)side);
    node_kernel<32, 16><<<NODE_GRID, TB>>>(
        egoA, side, egoB, Wg2, bg2, Wb2, bb2, all, 160);

    // ---- batched gather ----
    gather_kernel<<<(3 * BATCH * 44 + TB - 1) / TB, TB>>>(
        users, pos, neg, (float4*)d_out);
}

// round 3
// speedup vs baseline: 1.1669x; 1.1669x over previous
#include <cuda_runtime.h>
#include <cuda_bf16.h>
#include <math.h>

#define N_USERS   50000
#define N_ENT     100000
#define N_NODES   150000
#define N_EDGES   3000000
#define BATCH     8192
#define OUT_COLS  176
#define LEAKY     0.2f

// ---------------- scratch (device globals; no allocation allowed) ------------
__device__ float4 g_egoA4[N_NODES * 16];   // up to 64 floats/row
__device__ float4 g_egoB4[N_NODES * 16];
__device__ float4 g_side4[N_NODES * 16];
__device__ float4 g_all4 [N_NODES * 44];   // 176 floats/row

// ---------------- f32x2 packed helpers ---------------------------------------
__device__ __forceinline__ unsigned long long pk2(float a, float b) {
    unsigned long long r;
    asm("mov.b64 %0, {%1,%2};" : "=l"(r) : "f"(a), "f"(b));
    return r;
}
__device__ __forceinline__ void upk2(unsigned long long v, float& a, float& b) {
    asm("mov.b64 {%0,%1}, %2;" : "=f"(a), "=f"(b) : "l"(v));
}
__device__ __forceinline__ void ffma2(unsigned long long& acc,
                                      unsigned long long a,
                                      unsigned long long b) {
    asm("fma.rn.f32x2 %0, %1, %2, %0;" : "+l"(acc) : "l"(a), "l"(b));
}

// ---------------- init: concat embeddings -> egoA and all_emb[:,0:64] --------
__global__ void init_kernel(const float4* __restrict__ u4,
                            const float4* __restrict__ e4) {
    int gid = blockIdx.x * blockDim.x + threadIdx.x;
    if (gid >= N_NODES * 16) return;
    int r = gid >> 4;
    int c = gid & 15;
    float4 v = (r < N_USERS) ? u4[gid] : e4[gid - N_USERS * 16];
    g_egoA4[gid] = v;
    g_all4[r * 44 + c] = v;
}

// ---------------- edge phase: side[h] += A * ego[t] ---------------------------
// Each thread handles TWO float4 chunks of one edge (MLP=2, half the index loads).
template <int CH>  // CH float4 chunks per row; thread covers chunks c and c+CH/2
__global__ void edge_kernel(const int*   __restrict__ all_h,
                            const int*   __restrict__ all_t,
                            const float* __restrict__ A,
                            const float4* __restrict__ ego4,
                            float4* __restrict__ side4) {
    constexpr int TPE   = CH / 2;                    // threads per edge
    constexpr int SHIFT = (TPE == 8) ? 3 : 2;
    int gid = blockIdx.x * blockDim.x + threadIdx.x;
    int e = gid >> SHIFT;
    int c = gid & (TPE - 1);
    if (e >= N_EDGES) return;
    int   t = __ldg(all_t + e);
    int   h = __ldg(all_h + e);
    float a = __ldg(A + e);
    float4 v0 = __ldg(ego4 + (size_t)t * CH + c);
    float4 v1 = __ldg(ego4 + (size_t)t * CH + c + TPE);
    float4* p0 = side4 + (size_t)h * CH + c;
    float4* p1 = p0 + TPE;
    asm volatile("red.global.add.v4.f32 [%0], {%1,%2,%3,%4};"
                 :: "l"(p0), "f"(a * v0.x), "f"(a * v0.y), "f"(a * v0.z), "f"(a * v0.w)
                 : "memory");
    asm volatile("red.global.add.v4.f32 [%0], {%1,%2,%3,%4};"
                 :: "l"(p1), "f"(a * v1.x), "f"(a * v1.y), "f"(a * v1.z), "f"(a * v1.w)
                 : "memory");
}

// ---------------- node phase: two GEMMs + leaky + norm (packed f32x2) --------
// Block = 256 threads = R groups of DOUT threads; each group owns one row.
// Weights staged transposed+interleaved: sW4[j][i2] = {Wg[2i2][j], Wb[2i2][j],
//                                                      Wg[2i2+1][j], Wb[2i2+1][j]}
// Row padded by one float4 (16B) -> conflict-free LDS.128 across lanes.
template <int DIN, int DOUT>
__global__ void node_kernel(const float* __restrict__ ego_in,
                            const float* __restrict__ side,
                            float* __restrict__ ego_out,
                            const float* __restrict__ Wg,
                            const float* __restrict__ bg,
                            const float* __restrict__ Wb,
                            const float* __restrict__ bb,
                            float* __restrict__ all_emb,
                            int col_off) {
    constexpr int R  = 256 / DOUT;    // rows per block iteration
    constexpr int I2 = DIN / 2;       // packed-pair count

    __shared__ float4 sW4[DOUT][I2 + 1];
    __shared__ float4 sx4[R][I2];     // {xs_i, xb_i, xs_{i+1}, xb_{i+1}}
    __shared__ float2 sb2[DOUT];
    __shared__ float  swsum[R][2];

    int tid = threadIdx.x;

    // stage weights (coalesced global reads, one-time)
    for (int k = tid; k < DOUT * I2; k += 256) {
        int j  = k % DOUT;
        int i2 = k / DOUT;
        sW4[j][i2] = make_float4(Wg[(2 * i2)     * DOUT + j],
                                 Wb[(2 * i2)     * DOUT + j],
                                 Wg[(2 * i2 + 1) * DOUT + j],
                                 Wb[(2 * i2 + 1) * DOUT + j]);
    }
    if (tid < DOUT) sb2[tid] = make_float2(bg[tid], bb[tid]);
    __syncthreads();

    int g    = tid / DOUT;   // group (row slot)
    int j    = tid % DOUT;   // output column
    int lane = tid & 31;

    for (int base = blockIdx.x * R; base < N_NODES; base += gridDim.x * R) {
        int row = base + g;
        bool active = row < N_NODES;

        if (active) {
            for (int i2 = j; i2 < I2; i2 += DOUT) {
                float2 e2 = *reinterpret_cast<const float2*>(ego_in + (size_t)row * DIN + 2 * i2);
                float2 s2 = *reinterpret_cast<const float2*>(side   + (size_t)row * DIN + 2 * i2);
                sx4[g][i2] = make_float4(e2.x + s2.x, e2.x * s2.x,
                                         e2.y + s2.y, e2.y * s2.y);
            }
        }
        __syncthreads();

        float out = 0.f;
        if (active) {
            float2 b2 = sb2[j];
            unsigned long long acc = pk2(b2.x, b2.y);
            #pragma unroll
            for (int i2 = 0; i2 < I2; i2++) {
                float4 x = sx4[g][i2];
                float4 w = sW4[j][i2];
                ffma2(acc, pk2(x.x, x.y), pk2(w.x, w.y));
                ffma2(acc, pk2(x.z, x.w), pk2(w.z, w.w));
            }
            float sg, bi;
            upk2(acc, sg, bi);
            sg = sg > 0.f ? sg : LEAKY * sg;
            bi = bi > 0.f ? bi : LEAKY * bi;
            out = sg + bi;
        }

        // L2 norm over the DOUT outputs of this row
        float p = out * out;
        if (DOUT >= 64) {
            #pragma unroll
            for (int o = 16; o > 0; o >>= 1) p += __shfl_xor_sync(0xffffffffu, p, o);
            if (lane == 0) swsum[g][(tid >> 5) & 1] = p;
            __syncthreads();
            p = swsum[g][0] + swsum[g][1];
        } else {
            #pragma unroll
            for (int o = DOUT / 2; o > 0; o >>= 1) p += __shfl_xor_sync(0xffffffffu, p, o);
        }

        if (active) {
            float r  = sqrtf(p);
            float nv = out / fmaxf(r, 1e-12f);
            ego_out[(size_t)row * DOUT + j]            = out;  // un-normalized carries forward
            all_emb[(size_t)row * OUT_COLS + col_off + j] = nv;  // normalized goes to concat
        }
        __syncthreads();   // protect sx4/swsum reuse next iteration
    }
}

// ---------------- final gather: (u_e, pos_i_e, neg_i_e) ----------------------
__global__ void gather_kernel(const int* __restrict__ users,
                              const int* __restrict__ pos,
                              const int* __restrict__ neg,
                              float4* __restrict__ out4) {
    int gid = blockIdx.x * blockDim.x + threadIdx.x;
    if (gid >= 3 * BATCH * 44) return;
    int idx   = gid / 44;
    int c     = gid - idx * 44;
    int which = idx / BATCH;
    int b     = idx - which * BATCH;
    int row = (which == 0) ? users[b]
            : (which == 1) ? (N_USERS + pos[b])
                           : (N_USERS + neg[b]);
    out4[gid] = g_all4[row * 44 + c];
}

// -----------------------------------------------------------------------------
extern "C" void kernel_launch(void* const* d_in, const int* in_sizes, int n_in,
                              void* d_out, int out_size) {
    const int*   users = (const int*)  d_in[0];
    const int*   pos   = (const int*)  d_in[1];
    const int*   neg   = (const int*)  d_in[2];
    const int*   all_h = (const int*)  d_in[3];
    const int*   all_t = (const int*)  d_in[4];
    const float* Aval  = (const float*)d_in[5];
    const float* u_emb = (const float*)d_in[6];
    const float* e_emb = (const float*)d_in[7];
    const float* Wg0 = (const float*)d_in[8];
    const float* bg0 = (const float*)d_in[9];
    const float* Wb0 = (const float*)d_in[10];
    const float* bb0 = (const float*)d_in[11];
    const float* Wg1 = (const float*)d_in[12];
    const float* bg1 = (const float*)d_in[13];
    const float* Wb1 = (const float*)d_in[14];
    const float* bb1 = (const float*)d_in[15];
    const float* Wg2 = (const float*)d_in[16];
    const float* bg2 = (const float*)d_in[17];
    const float* Wb2 = (const float*)d_in[18];
    const float* bb2 = (const float*)d_in[19];

    void *pA, *pB, *pS, *pAll;
    cudaGetSymbolAddress(&pA,   g_egoA4);
    cudaGetSymbolAddress(&pB,   g_egoB4);
    cudaGetSymbolAddress(&pS,   g_side4);
    cudaGetSymbolAddress(&pAll, g_all4);
    float* egoA = (float*)pA;
    float* egoB = (float*)pB;
    float* side = (float*)pS;
    float* all  = (float*)pAll;

    const int TB = 256;
    const int NODE_GRID = 148 * 6;

    // init: ego0 + all_emb[:,0:64]
    init_kernel<<<(N_NODES * 16 + TB - 1) / TB, TB>>>(
        (const float4*)u_emb, (const float4*)e_emb);

    // ---- layer 0: 64 -> 64 (egoA -> egoB), norm to cols [64,128) ----
    cudaMemsetAsync(side, 0, (size_t)N_NODES * 64 * sizeof(float));
    edge_kernel<16><<<(N_EDGES * 8 + TB - 1) / TB, TB>>>(
        all_h, all_t, Aval, (const float4*)egoA, (float4*)side);
    node_kernel<64, 64><<<NODE_GRID, TB>>>(
        egoA, side, egoB, Wg0, bg0, Wb0, bb0, all, 64);

    // ---- layer 1: 64 -> 32 (egoB -> egoA), norm to cols [128,160) ----
    cudaMemsetAsync(side, 0, (size_t)N_NODES * 64 * sizeof(float));
    edge_kernel<16><<<(N_EDGES * 8 + TB - 1) / TB, TB>>>(
        all_h, all_t, Aval, (const float4*)egoB, (float4*)side);
    node_kernel<64, 32><<<NODE_GRID, TB>>>(
        egoB, side, egoA, Wg1, bg1, Wb1, bb1, all, 128);

    // ---- layer 2: 32 -> 16 (egoA -> egoB), norm to cols [160,176) ----
    cudaMemsetAsync(side, 0, (size_t)N_NODES * 32 * sizeof(float));
    edge_kernel<8><<<(N_EDGES * 4 + TB - 1) / TB, TB>>>(
        all_h, all_t, Aval, (const float4*)egoA, (float4*)side);
    node_kernel<32, 16><<<NODE_GRID, TB>>>(
        egoA, side, egoB, Wg2, bg2, Wb2, bb2, all, 160);

    // ---- batched gather ----
    gather_kernel<<<(3 * BATCH * 44 + TB - 1) / TB, TB>>>(
        users, pos, neg, (float4*)d_out);
}

// round 4
// speedup vs baseline: 1.7556x; 1.5045x over previous
#include <cuda_runtime.h>
#include <cuda_bf16.h>
#include <math.h>

#define N_USERS   50000
#define N_ENT     100000
#define N_NODES   150000
#define N_EDGES   3000000
#define BATCH     8192
#define OUT_COLS  176
#define LEAKY     0.2f

// ---------------- scratch (device globals) -----------------------------------
__device__ float4 g_egoA4[N_NODES * 16];        // up to 64 floats/row
__device__ float4 g_egoB4[N_NODES * 16];
__device__ float4 g_x4  [N_NODES * 32];         // packed {xs,xb} pairs (max 64in)
__device__ float4 g_all4[N_NODES * 44];         // 176 floats/row
__device__ long long g_pairs[N_EDGES];          // {a:hi32, t:lo32} sorted by h
__device__ int g_rowptr[N_NODES + 1];
__device__ int g_cursor[N_NODES];               // deg -> cursor
__device__ int g_partial[256];                  // scan partials

#define SCAN_BLOCKS 147                          // 147*1024 >= 150000

// ---------------- f32x2 packed helpers ---------------------------------------
__device__ __forceinline__ unsigned long long pk2(float a, float b) {
    unsigned long long r;
    asm("mov.b64 %0, {%1,%2};" : "=l"(r) : "f"(a), "f"(b));
    return r;
}
__device__ __forceinline__ void upk2(unsigned long long v, float& a, float& b) {
    asm("mov.b64 {%0,%1}, %2;" : "=f"(a), "=f"(b) : "l"(v));
}
__device__ __forceinline__ void ffma2(unsigned long long& acc,
                                      unsigned long long a,
                                      unsigned long long b) {
    asm("fma.rn.f32x2 %0, %1, %2, %0;" : "+l"(acc) : "l"(a), "l"(b));
}

// ---------------- init: concat embeddings -> egoA and all_emb[:,0:64] --------
__global__ void init_kernel(const float4* __restrict__ u4,
                            const float4* __restrict__ e4) {
    int gid = blockIdx.x * blockDim.x + threadIdx.x;
    if (gid >= N_NODES * 16) return;
    int r = gid >> 4;
    int c = gid & 15;
    float4 v = (r < N_USERS) ? u4[gid] : e4[gid - N_USERS * 16];
    g_egoA4[gid] = v;
    g_all4[r * 44 + c] = v;
}

// ================= CSR build ==================================================
__global__ void hist_kernel(const int* __restrict__ all_h) {
    int e = blockIdx.x * blockDim.x + threadIdx.x;
    if (e < N_EDGES) atomicAdd(&g_cursor[all_h[e]], 1);
}

// pass1: per-block sums of 1024 degrees
__global__ void scan_pass1() {
    __shared__ int sm[256];
    int tid = threadIdx.x;
    int base = blockIdx.x * 1024 + tid * 4;
    int s = 0;
    #pragma unroll
    for (int k = 0; k < 4; k++) {
        int idx = base + k;
        if (idx < N_NODES) s += g_cursor[idx];
    }
    sm[tid] = s; __syncthreads();
    for (int o = 128; o > 0; o >>= 1) {
        if (tid < o) sm[tid] += sm[tid + o];
        __syncthreads();
    }
    if (tid == 0) g_partial[blockIdx.x] = sm[0];
}

// pass2: exclusive scan of block partials (single block)
__global__ void scan_pass2() {
    __shared__ int sm[256];
    int tid = threadIdx.x;
    int v = (tid < SCAN_BLOCKS) ? g_partial[tid] : 0;
    sm[tid] = v; __syncthreads();
    for (int o = 1; o < 256; o <<= 1) {
        int t = (tid >= o) ? sm[tid - o] : 0;
        __syncthreads();
        sm[tid] += t;
        __syncthreads();
    }
    if (tid < SCAN_BLOCKS) g_partial[tid] = sm[tid] - v;   // exclusive
    if (tid == 0) g_rowptr[N_NODES] = N_EDGES;
}

// pass3: write rowptr + reset cursor to row starts
__global__ void scan_pass3() {
    __shared__ int sm[256];
    int tid = threadIdx.x;
    int base = blockIdx.x * 1024 + tid * 4;
    int d[4]; int s = 0;
    #pragma unroll
    for (int k = 0; k < 4; k++) {
        int idx = base + k;
        d[k] = (idx < N_NODES) ? g_cursor[idx] : 0;
        s += d[k];
    }
    sm[tid] = s; __syncthreads();
    for (int o = 1; o < 256; o <<= 1) {
        int t = (tid >= o) ? sm[tid - o] : 0;
        __syncthreads();
        sm[tid] += t;
        __syncthreads();
    }
    int run = g_partial[blockIdx.x] + sm[tid] - s;   // exclusive within grid
    #pragma unroll
    for (int k = 0; k < 4; k++) {
        int idx = base + k;
        if (idx < N_NODES) {
            g_rowptr[idx] = run;
            g_cursor[idx] = run;
            run += d[k];
        }
    }
}

__global__ void fill_kernel(const int* __restrict__ all_h,
                            const int* __restrict__ all_t,
                            const float* __restrict__ A) {
    int e = blockIdx.x * blockDim.x + threadIdx.x;
    if (e >= N_EDGES) return;
    int h = all_h[e];
    int p = atomicAdd(&g_cursor[h], 1);
    unsigned long long q = (unsigned long long)(unsigned)all_t[e]
                         | ((unsigned long long)__float_as_uint(A[e]) << 32);
    g_pairs[p] = (long long)q;
}

// ================= aggregation (warp per node) ================================
// DIN=64: lane owns inputs (2*lane, 2*lane+1) as float2; writes x4[n*32+lane].
__global__ void agg64_kernel(const float2* __restrict__ ego2,
                             float4* __restrict__ x4) {
    int gw = (blockIdx.x * blockDim.x + threadIdx.x) >> 5;
    int lane = threadIdx.x & 31;
    if (gw >= N_NODES) return;
    int s   = __ldg(g_rowptr + gw);
    int end = __ldg(g_rowptr + gw + 1);
    float ax = 0.f, ay = 0.f;
    int e = s;
    for (; e + 4 <= end; e += 4) {
        long long q0 = __ldg(g_pairs + e),     q1 = __ldg(g_pairs + e + 1);
        long long q2 = __ldg(g_pairs + e + 2), q3 = __ldg(g_pairs + e + 3);
        int   t0 = (int)(unsigned)q0; float a0 = __uint_as_float((unsigned)((unsigned long long)q0 >> 32));
        int   t1 = (int)(unsigned)q1; float a1 = __uint_as_float((unsigned)((unsigned long long)q1 >> 32));
        int   t2 = (int)(unsigned)q2; float a2 = __uint_as_float((unsigned)((unsigned long long)q2 >> 32));
        int   t3 = (int)(unsigned)q3; float a3 = __uint_as_float((unsigned)((unsigned long long)q3 >> 32));
        float2 v0 = __ldg(ego2 + (size_t)t0 * 32 + lane);
        float2 v1 = __ldg(ego2 + (size_t)t1 * 32 + lane);
        float2 v2 = __ldg(ego2 + (size_t)t2 * 32 + lane);
        float2 v3 = __ldg(ego2 + (size_t)t3 * 32 + lane);
        ax += a0 * v0.x; ay += a0 * v0.y;
        ax += a1 * v1.x; ay += a1 * v1.y;
        ax += a2 * v2.x; ay += a2 * v2.y;
        ax += a3 * v3.x; ay += a3 * v3.y;
    }
    for (; e < end; e++) {
        long long q = __ldg(g_pairs + e);
        int t = (int)(unsigned)q;
        float a = __uint_as_float((unsigned)((unsigned long long)q >> 32));
        float2 v = __ldg(ego2 + (size_t)t * 32 + lane);
        ax += a * v.x; ay += a * v.y;
    }
    float2 eg = __ldg(ego2 + (size_t)gw * 32 + lane);
    x4[(size_t)gw * 32 + lane] =
        make_float4(eg.x + ax, eg.x * ax, eg.y + ay, eg.y * ay);
}

// DIN=32: lane owns input lane as float; writes x2[n*32+lane] = {xs, xb}.
__global__ void agg32_kernel(const float* __restrict__ ego1,
                             float2* __restrict__ x2) {
    int gw = (blockIdx.x * blockDim.x + threadIdx.x) >> 5;
    int lane = threadIdx.x & 31;
    if (gw >= N_NODES) return;
    int s   = __ldg(g_rowptr + gw);
    int end = __ldg(g_rowptr + gw + 1);
    float acc = 0.f;
    int e = s;
    for (; e + 4 <= end; e += 4) {
        long long q0 = __ldg(g_pairs + e),     q1 = __ldg(g_pairs + e + 1);
        long long q2 = __ldg(g_pairs + e + 2), q3 = __ldg(g_pairs + e + 3);
        int   t0 = (int)(unsigned)q0; float a0 = __uint_as_float((unsigned)((unsigned long long)q0 >> 32));
        int   t1 = (int)(unsigned)q1; float a1 = __uint_as_float((unsigned)((unsigned long long)q1 >> 32));
        int   t2 = (int)(unsigned)q2; float a2 = __uint_as_float((unsigned)((unsigned long long)q2 >> 32));
        int   t3 = (int)(unsigned)q3; float a3 = __uint_as_float((unsigned)((unsigned long long)q3 >> 32));
        float v0 = __ldg(ego1 + (size_t)t0 * 32 + lane);
        float v1 = __ldg(ego1 + (size_t)t1 * 32 + lane);
        float v2 = __ldg(ego1 + (size_t)t2 * 32 + lane);
        float v3 = __ldg(ego1 + (size_t)t3 * 32 + lane);
        acc += a0 * v0 + a1 * v1 + a2 * v2 + a3 * v3;
    }
    for (; e < end; e++) {
        long long q = __ldg(g_pairs + e);
        int t = (int)(unsigned)q;
        float a = __uint_as_float((unsigned)((unsigned long long)q >> 32));
        acc += a * __ldg(ego1 + (size_t)t * 32 + lane);
    }
    float eg = __ldg(ego1 + (size_t)gw * 32 + lane);
    x2[(size_t)gw * 32 + lane] = make_float2(eg + acc, eg * acc);
}

// ================= GEMM + leaky + norm (row-batched, packed f32x2) ============
// x4 input rows: I2 = DIN/2 float4 per row, each = {xs_2i,xb_2i,xs_2i+1,xb_2i+1}
template <int DIN, int DOUT, int R>
__global__ void gemm_kernel(const float4* __restrict__ x4,
                            float* __restrict__ ego_out,
                            const float* __restrict__ Wg,
                            const float* __restrict__ bg,
                            const float* __restrict__ Wb,
                            const float* __restrict__ bb,
                            float* __restrict__ all_emb,
                            int col_off) {
    constexpr int I2   = DIN / 2;
    constexpr int JG   = 256 / DOUT;    // row-groups per block
    constexpr int ROWS = JG * R;

    __shared__ float4 sW4[DOUT][I2 + 1];
    __shared__ float4 sx4[ROWS][I2];
    __shared__ float2 sb2[DOUT];
    __shared__ float  swp[JG][2][R];    // only used when DOUT==64

    int tid = threadIdx.x;
    // stage weights once per block: sW4[j][i2] = {Wg[2i2][j],Wb[2i2][j],Wg[2i2+1][j],Wb[2i2+1][j]}
    for (int k = tid; k < DOUT * I2; k += 256) {
        int j  = k % DOUT;
        int i2 = k / DOUT;
        sW4[j][i2] = make_float4(Wg[(2 * i2)     * DOUT + j],
                                 Wb[(2 * i2)     * DOUT + j],
                                 Wg[(2 * i2 + 1) * DOUT + j],
                                 Wb[(2 * i2 + 1) * DOUT + j]);
    }
    if (tid < DOUT) sb2[tid] = make_float2(bg[tid], bb[tid]);
    __syncthreads();

    int rg   = tid / DOUT;
    int j    = tid % DOUT;
    int lane = tid & 31;
    float2 b2 = sb2[j];

    for (int base = blockIdx.x * ROWS; base < N_NODES; base += gridDim.x * ROWS) {
        // stage x rows [base, base+ROWS)
        {
            const float4* src = x4 + (size_t)base * I2;
            int limit = (N_NODES - base) * I2;
            int total = ROWS * I2;
            for (int k = tid; k < total; k += 256)
                if (k < limit) ((float4*)sx4)[k] = src[k];
        }
        __syncthreads();

        unsigned long long acc[R];
        #pragma unroll
        for (int rr = 0; rr < R; rr++) acc[rr] = pk2(b2.x, b2.y);

        #pragma unroll
        for (int i2 = 0; i2 < I2; i2++) {
            float4 w = sW4[j][i2];
            unsigned long long w01 = pk2(w.x, w.y);
            unsigned long long w23 = pk2(w.z, w.w);
            #pragma unroll
            for (int rr = 0; rr < R; rr++) {
                float4 x = sx4[rg * R + rr][i2];
                ffma2(acc[rr], pk2(x.x, x.y), w01);
                ffma2(acc[rr], pk2(x.z, x.w), w23);
            }
        }

        float outv[R], tot[R];
        #pragma unroll
        for (int rr = 0; rr < R; rr++) {
            float sg, bi;
            upk2(acc[rr], sg, bi);
            sg = sg > 0.f ? sg : LEAKY * sg;
            bi = bi > 0.f ? bi : LEAKY * bi;
            outv[rr] = sg + bi;
        }

        if (DOUT == 64) {
            #pragma unroll
            for (int rr = 0; rr < R; rr++) {
                float p = outv[rr] * outv[rr];
                #pragma unroll
                for (int o = 16; o > 0; o >>= 1)
                    p += __shfl_xor_sync(0xffffffffu, p, o);
                if (lane == 0) swp[rg][(j >> 5) & 1][rr] = p;
            }
            __syncthreads();
            #pragma unroll
            for (int rr = 0; rr < R; rr++)
                tot[rr] = swp[rg][0][rr] + swp[rg][1][rr];
        } else {
            #pragma unroll
            for (int rr = 0; rr < R; rr++) {
                float p = outv[rr] * outv[rr];
                #pragma unroll
                for (int o = DOUT / 2; o > 0; o >>= 1)
                    p += __shfl_xor_sync(0xffffffffu, p, o);
                tot[rr] = p;
            }
        }

        #pragma unroll
        for (int rr = 0; rr < R; rr++) {
            int row = base + rg * R + rr;
            if (row < N_NODES) {
                float nv = outv[rr] / fmaxf(sqrtf(tot[rr]), 1e-12f);
                ego_out[(size_t)row * DOUT + j] = outv[rr];
                all_emb[(size_t)row * OUT_COLS + col_off + j] = nv;
            }
        }
        __syncthreads();   // protect sx4/swp reuse
    }
}

// ---------------- final gather: (u_e, pos_i_e, neg_i_e) ----------------------
__global__ void gather_kernel(const int* __restrict__ users,
                              const int* __restrict__ pos,
                              const int* __restrict__ neg,
                              float4* __restrict__ out4) {
    int gid = blockIdx.x * blockDim.x + threadIdx.x;
    if (gid >= 3 * BATCH * 44) return;
    int idx   = gid / 44;
    int c     = gid - idx * 44;
    int which = idx / BATCH;
    int b     = idx - which * BATCH;
    int row = (which == 0) ? users[b]
            : (which == 1) ? (N_USERS + pos[b])
                           : (N_USERS + neg[b]);
    out4[gid] = g_all4[row * 44 + c];
}

// -----------------------------------------------------------------------------
extern "C" void kernel_launch(void* const* d_in, const int* in_sizes, int n_in,
                              void* d_out, int out_size) {
    const int*   users = (const int*)  d_in[0];
    const int*   pos   = (const int*)  d_in[1];
    const int*   neg   = (const int*)  d_in[2];
    const int*   all_h = (const int*)  d_in[3];
    const int*   all_t = (const int*)  d_in[4];
    const float* Aval  = (const float*)d_in[5];
    const float* u_emb = (const float*)d_in[6];
    const float* e_emb = (const float*)d_in[7];
    const float* Wg0 = (const float*)d_in[8];
    const float* bg0 = (const float*)d_in[9];
    const float* Wb0 = (const float*)d_in[10];
    const float* bb0 = (const float*)d_in[11];
    const float* Wg1 = (const float*)d_in[12];
    const float* bg1 = (const float*)d_in[13];
    const float* Wb1 = (const float*)d_in[14];
    const float* bb1 = (const float*)d_in[15];
    const float* Wg2 = (const float*)d_in[16];
    const float* bg2 = (const float*)d_in[17];
    const float* Wb2 = (const float*)d_in[18];
    const float* bb2 = (const float*)d_in[19];

    void *pA, *pB, *pX, *pAll, *pCur;
    cudaGetSymbolAddress(&pA,   g_egoA4);
    cudaGetSymbolAddress(&pB,   g_egoB4);
    cudaGetSymbolAddress(&pX,   g_x4);
    cudaGetSymbolAddress(&pAll, g_all4);
    cudaGetSymbolAddress(&pCur, g_cursor);
    float* egoA = (float*)pA;
    float* egoB = (float*)pB;
    float4* x4  = (float4*)pX;
    float* all  = (float*)pAll;

    const int TB = 256;
    const int GEMM_GRID = 148 * 8;
    const int AGG_GRID  = (N_NODES * 32 + TB - 1) / TB;

    // init: ego0 + all_emb[:,0:64]
    init_kernel<<<(N_NODES * 16 + TB - 1) / TB, TB>>>(
        (const float4*)u_emb, (const float4*)e_emb);

    // ---- CSR build (once, reused by all 3 layers) ----
    cudaMemsetAsync(pCur, 0, N_NODES * sizeof(int));
    hist_kernel<<<(N_EDGES + TB - 1) / TB, TB>>>(all_h);
    scan_pass1<<<SCAN_BLOCKS, 256>>>();
    scan_pass2<<<1, 256>>>();
    scan_pass3<<<SCAN_BLOCKS, 256>>>();
    fill_kernel<<<(N_EDGES + TB - 1) / TB, TB>>>(all_h, all_t, Aval);

    // ---- layer 0: 64 -> 64 (egoA -> egoB), norm to cols [64,128) ----
    agg64_kernel<<<AGG_GRID, TB>>>((const float2*)egoA, x4);
    gemm_kernel<64, 64, 4><<<GEMM_GRID, TB>>>(
        x4, egoB, Wg0, bg0, Wb0, bb0, all, 64);

    // ---- layer 1: 64 -> 32 (egoB -> egoA), norm to cols [128,160) ----
    agg64_kernel<<<AGG_GRID, TB>>>((const float2*)egoB, x4);
    gemm_kernel<64, 32, 4><<<GEMM_GRID, TB>>>(
        x4, egoA, Wg1, bg1, Wb1, bb1, all, 128);

    // ---- layer 2: 32 -> 16 (egoA -> egoB), norm to cols [160,176) ----
    agg32_kernel<<<AGG_GRID, TB>>>((const float*)egoA, (float2*)x4);
    gemm_kernel<32, 16, 4><<<GEMM_GRID, TB>>>(
        x4, egoB, Wg2, bg2, Wb2, bb2, all, 160);

    // ---- batched gather ----
    gather_kernel<<<(3 * BATCH * 44 + TB - 1) / TB, TB>>>(
        users, pos, neg, (float4*)d_out);
}

// round 5
// speedup vs baseline: 1.9845x; 1.1304x over previous
#include <cuda_runtime.h>
#include <cuda_bf16.h>
#include <math.h>

#define N_USERS   50000
#define N_ENT     100000
#define N_NODES   150000
#define N_EDGES   3000000
#define BATCH     8192
#define OUT_COLS  176
#define LEAKY     0.2f

// ---------------- scratch (device globals) -----------------------------------
__device__ float4 g_egoA4[N_NODES * 16];        // layer outputs (<=64 floats/row)
__device__ float4 g_egoB4[N_NODES * 16];
__device__ float4 g_x4  [N_NODES * 32];         // packed {xs,xb} pairs (max 64in)
__device__ float4 g_all4[N_NODES * 44];         // cols [64,176) used
__device__ long long g_pairs[N_EDGES];          // {a:hi32, t:lo32} grouped by h
__device__ int g_rowptr[N_NODES + 1];
__device__ int g_cursor[N_NODES];
__device__ int g_partial[256];

#define SCAN_BLOCKS 147                          // 147*1024 >= 150000

// ---------------- f32x2 packed helpers ---------------------------------------
__device__ __forceinline__ unsigned long long pk2(float a, float b) {
    unsigned long long r;
    asm("mov.b64 %0, {%1,%2};" : "=l"(r) : "f"(a), "f"(b));
    return r;
}
__device__ __forceinline__ void upk2(unsigned long long v, float& a, float& b) {
    asm("mov.b64 {%0,%1}, %2;" : "=f"(a), "=f"(b) : "l"(v));
}
__device__ __forceinline__ void ffma2(unsigned long long& acc,
                                      unsigned long long a,
                                      unsigned long long b) {
    asm("fma.rn.f32x2 %0, %1, %2, %0;" : "+l"(acc) : "l"(a), "l"(b));
}

// ================= CSR build ==================================================
__global__ void hist_kernel(const int* __restrict__ all_h) {
    int e = blockIdx.x * blockDim.x + threadIdx.x;
    if (e < N_EDGES) atomicAdd(&g_cursor[all_h[e]], 1);
}

__global__ void scan_pass1() {
    __shared__ int sm[256];
    int tid = threadIdx.x;
    int base = blockIdx.x * 1024 + tid * 4;
    int s = 0;
    #pragma unroll
    for (int k = 0; k < 4; k++) {
        int idx = base + k;
        if (idx < N_NODES) s += g_cursor[idx];
    }
    sm[tid] = s; __syncthreads();
    for (int o = 128; o > 0; o >>= 1) {
        if (tid < o) sm[tid] += sm[tid + o];
        __syncthreads();
    }
    if (tid == 0) g_partial[blockIdx.x] = sm[0];
}

__global__ void scan_pass2() {
    __shared__ int sm[256];
    int tid = threadIdx.x;
    int v = (tid < SCAN_BLOCKS) ? g_partial[tid] : 0;
    sm[tid] = v; __syncthreads();
    for (int o = 1; o < 256; o <<= 1) {
        int t = (tid >= o) ? sm[tid - o] : 0;
        __syncthreads();
        sm[tid] += t;
        __syncthreads();
    }
    if (tid < SCAN_BLOCKS) g_partial[tid] = sm[tid] - v;   // exclusive
    if (tid == 0) g_rowptr[N_NODES] = N_EDGES;
}

__global__ void scan_pass3() {
    __shared__ int sm[256];
    int tid = threadIdx.x;
    int base = blockIdx.x * 1024 + tid * 4;
    int d[4]; int s = 0;
    #pragma unroll
    for (int k = 0; k < 4; k++) {
        int idx = base + k;
        d[k] = (idx < N_NODES) ? g_cursor[idx] : 0;
        s += d[k];
    }
    sm[tid] = s; __syncthreads();
    for (int o = 1; o < 256; o <<= 1) {
        int t = (tid >= o) ? sm[tid - o] : 0;
        __syncthreads();
        sm[tid] += t;
        __syncthreads();
    }
    int run = g_partial[blockIdx.x] + sm[tid] - s;
    #pragma unroll
    for (int k = 0; k < 4; k++) {
        int idx = base + k;
        if (idx < N_NODES) {
            g_rowptr[idx] = run;
            g_cursor[idx] = run;
            run += d[k];
        }
    }
}

__global__ void fill_kernel(const int* __restrict__ all_h,
                            const int* __restrict__ all_t,
                            const float* __restrict__ A) {
    int e = blockIdx.x * blockDim.x + threadIdx.x;
    if (e >= N_EDGES) return;
    int h = all_h[e];
    int p = atomicAdd(&g_cursor[h], 1);
    unsigned long long q = (unsigned long long)(unsigned)all_t[e]
                         | ((unsigned long long)__float_as_uint(A[e]) << 32);
    g_pairs[p] = (long long)q;
}

// ================= aggregation (warp per node) ================================
__device__ __forceinline__ void unpack_pair(long long q, int& t, float& a) {
    t = (int)(unsigned)q;
    a = __uint_as_float((unsigned)((unsigned long long)q >> 32));
}

// layer-0 variant: ego read from split user/entity tables.
__global__ void agg64_split_kernel(const float2* __restrict__ u2,
                                   const float2* __restrict__ e2,
                                   float4* __restrict__ x4) {
    int gw = (blockIdx.x * blockDim.x + threadIdx.x) >> 5;
    int lane = threadIdx.x & 31;
    if (gw >= N_NODES) return;
    int s   = __ldg(g_rowptr + gw);
    int end = __ldg(g_rowptr + gw + 1);
    float ax = 0.f, ay = 0.f;
    int e = s;
    for (; e + 4 <= end; e += 4) {
        int t0, t1, t2, t3; float a0, a1, a2, a3;
        unpack_pair(__ldg(g_pairs + e),     t0, a0);
        unpack_pair(__ldg(g_pairs + e + 1), t1, a1);
        unpack_pair(__ldg(g_pairs + e + 2), t2, a2);
        unpack_pair(__ldg(g_pairs + e + 3), t3, a3);
        float2 v0 = (t0 < N_USERS) ? __ldg(u2 + (size_t)t0 * 32 + lane)
                                   : __ldg(e2 + (size_t)(t0 - N_USERS) * 32 + lane);
        float2 v1 = (t1 < N_USERS) ? __ldg(u2 + (size_t)t1 * 32 + lane)
                                   : __ldg(e2 + (size_t)(t1 - N_USERS) * 32 + lane);
        float2 v2 = (t2 < N_USERS) ? __ldg(u2 + (size_t)t2 * 32 + lane)
                                   : __ldg(e2 + (size_t)(t2 - N_USERS) * 32 + lane);
        float2 v3 = (t3 < N_USERS) ? __ldg(u2 + (size_t)t3 * 32 + lane)
                                   : __ldg(e2 + (size_t)(t3 - N_USERS) * 32 + lane);
        ax += a0 * v0.x; ay += a0 * v0.y;
        ax += a1 * v1.x; ay += a1 * v1.y;
        ax += a2 * v2.x; ay += a2 * v2.y;
        ax += a3 * v3.x; ay += a3 * v3.y;
    }
    for (; e < end; e++) {
        int t; float a;
        unpack_pair(__ldg(g_pairs + e), t, a);
        float2 v = (t < N_USERS) ? __ldg(u2 + (size_t)t * 32 + lane)
                                 : __ldg(e2 + (size_t)(t - N_USERS) * 32 + lane);
        ax += a * v.x; ay += a * v.y;
    }
    float2 eg = (gw < N_USERS) ? __ldg(u2 + (size_t)gw * 32 + lane)
                               : __ldg(e2 + (size_t)(gw - N_USERS) * 32 + lane);
    x4[(size_t)gw * 32 + lane] =
        make_float4(eg.x + ax, eg.x * ax, eg.y + ay, eg.y * ay);
}

__global__ void agg64_kernel(const float2* __restrict__ ego2,
                             float4* __restrict__ x4) {
    int gw = (blockIdx.x * blockDim.x + threadIdx.x) >> 5;
    int lane = threadIdx.x & 31;
    if (gw >= N_NODES) return;
    int s   = __ldg(g_rowptr + gw);
    int end = __ldg(g_rowptr + gw + 1);
    float ax = 0.f, ay = 0.f;
    int e = s;
    for (; e + 4 <= end; e += 4) {
        int t0, t1, t2, t3; float a0, a1, a2, a3;
        unpack_pair(__ldg(g_pairs + e),     t0, a0);
        unpack_pair(__ldg(g_pairs + e + 1), t1, a1);
        unpack_pair(__ldg(g_pairs + e + 2), t2, a2);
        unpack_pair(__ldg(g_pairs + e + 3), t3, a3);
        float2 v0 = __ldg(ego2 + (size_t)t0 * 32 + lane);
        float2 v1 = __ldg(ego2 + (size_t)t1 * 32 + lane);
        float2 v2 = __ldg(ego2 + (size_t)t2 * 32 + lane);
        float2 v3 = __ldg(ego2 + (size_t)t3 * 32 + lane);
        ax += a0 * v0.x; ay += a0 * v0.y;
        ax += a1 * v1.x; ay += a1 * v1.y;
        ax += a2 * v2.x; ay += a2 * v2.y;
        ax += a3 * v3.x; ay += a3 * v3.y;
    }
    for (; e < end; e++) {
        int t; float a;
        unpack_pair(__ldg(g_pairs + e), t, a);
        float2 v = __ldg(ego2 + (size_t)t * 32 + lane);
        ax += a * v.x; ay += a * v.y;
    }
    float2 eg = __ldg(ego2 + (size_t)gw * 32 + lane);
    x4[(size_t)gw * 32 + lane] =
        make_float4(eg.x + ax, eg.x * ax, eg.y + ay, eg.y * ay);
}

__global__ void agg32_kernel(const float* __restrict__ ego1,
                             float2* __restrict__ x2) {
    int gw = (blockIdx.x * blockDim.x + threadIdx.x) >> 5;
    int lane = threadIdx.x & 31;
    if (gw >= N_NODES) return;
    int s   = __ldg(g_rowptr + gw);
    int end = __ldg(g_rowptr + gw + 1);
    float acc = 0.f;
    int e = s;
    for (; e + 4 <= end; e += 4) {
        int t0, t1, t2, t3; float a0, a1, a2, a3;
        unpack_pair(__ldg(g_pairs + e),     t0, a0);
        unpack_pair(__ldg(g_pairs + e + 1), t1, a1);
        unpack_pair(__ldg(g_pairs + e + 2), t2, a2);
        unpack_pair(__ldg(g_pairs + e + 3), t3, a3);
        float v0 = __ldg(ego1 + (size_t)t0 * 32 + lane);
        float v1 = __ldg(ego1 + (size_t)t1 * 32 + lane);
        float v2 = __ldg(ego1 + (size_t)t2 * 32 + lane);
        float v3 = __ldg(ego1 + (size_t)t3 * 32 + lane);
        acc += a0 * v0 + a1 * v1 + a2 * v2 + a3 * v3;
    }
    for (; e < end; e++) {
        int t; float a;
        unpack_pair(__ldg(g_pairs + e), t, a);
        acc += a * __ldg(ego1 + (size_t)t * 32 + lane);
    }
    float eg = __ldg(ego1 + (size_t)gw * 32 + lane);
    x2[(size_t)gw * 32 + lane] = make_float2(eg + acc, eg * acc);
}

// ================= GEMM + leaky + norm (2-col threads, packed f32x2) ==========
// Thread j' in a JW-thread row-group computes output columns j' and j'+JW.
template <int DIN, int DOUT, int R>
__global__ void __launch_bounds__(256)
gemm_kernel(const float4* __restrict__ x4,
            float* __restrict__ ego_out,
            const float* __restrict__ Wg,
            const float* __restrict__ bg,
            const float* __restrict__ Wb,
            const float* __restrict__ bb,
            float* __restrict__ all_emb,
            int col_off) {
    constexpr int I2   = DIN / 2;
    constexpr int JW   = DOUT / 2;      // threads per row-group
    constexpr int JG   = 256 / JW;      // row-groups per block
    constexpr int ROWS = JG * R;

    extern __shared__ float4 dyn4[];
    float4* sWa   = dyn4;                       // [JW][I2+1]
    float4* sWb   = sWa + JW * (I2 + 1);        // [JW][I2+1]
    float4* sx    = sWb + JW * (I2 + 1);        // [ROWS][I2]
    float4* sbias = sx + ROWS * I2;             // [JW]

    int tid = threadIdx.x;
    // stage weights once: sWa[j][i2] = {Wg[2i2][j],Wb[2i2][j],Wg[2i2+1][j],Wb[2i2+1][j]}
    for (int k = tid; k < JW * I2; k += 256) {
        int j  = k % JW;
        int i2 = k / JW;
        sWa[j * (I2 + 1) + i2] = make_float4(Wg[(2 * i2)     * DOUT + j],
                                             Wb[(2 * i2)     * DOUT + j],
                                             Wg[(2 * i2 + 1) * DOUT + j],
                                             Wb[(2 * i2 + 1) * DOUT + j]);
        int j2 = j + JW;
        sWb[j * (I2 + 1) + i2] = make_float4(Wg[(2 * i2)     * DOUT + j2],
                                             Wb[(2 * i2)     * DOUT + j2],
                                             Wg[(2 * i2 + 1) * DOUT + j2],
                                             Wb[(2 * i2 + 1) * DOUT + j2]);
    }
    if (tid < JW) sbias[tid] = make_float4(bg[tid], bb[tid], bg[tid + JW], bb[tid + JW]);
    __syncthreads();

    int rg = tid / JW;
    int j  = tid % JW;
    float4 bia = sbias[j];

    for (int base = blockIdx.x * ROWS; base < N_NODES; base += gridDim.x * ROWS) {
        // stage x rows [base, base+ROWS)
        {
            const float4* src = x4 + (size_t)base * I2;
            int limit = (N_NODES - base) * I2;
            int total = ROWS * I2;
            for (int k = tid; k < total; k += 256)
                if (k < limit) sx[k] = src[k];
        }
        __syncthreads();

        unsigned long long acca[R], accb[R];
        #pragma unroll
        for (int rr = 0; rr < R; rr++) {
            acca[rr] = pk2(bia.x, bia.y);
            accb[rr] = pk2(bia.z, bia.w);
        }

        #pragma unroll
        for (int i2 = 0; i2 < I2; i2++) {
            float4 wa = sWa[j * (I2 + 1) + i2];
            float4 wb = sWb[j * (I2 + 1) + i2];
            unsigned long long wa01 = pk2(wa.x, wa.y), wa23 = pk2(wa.z, wa.w);
            unsigned long long wb01 = pk2(wb.x, wb.y), wb23 = pk2(wb.z, wb.w);
            #pragma unroll
            for (int rr = 0; rr < R; rr++) {
                float4 x = sx[(rg * R + rr) * I2 + i2];
                unsigned long long x01 = pk2(x.x, x.y), x23 = pk2(x.z, x.w);
                ffma2(acca[rr], x01, wa01);
                ffma2(acca[rr], x23, wa23);
                ffma2(accb[rr], x01, wb01);
                ffma2(accb[rr], x23, wb23);
            }
        }

        #pragma unroll
        for (int rr = 0; rr < R; rr++) {
            float sga, bia_, sgb, bib;
            upk2(acca[rr], sga, bia_);
            upk2(accb[rr], sgb, bib);
            sga = sga > 0.f ? sga : LEAKY * sga;
            bia_ = bia_ > 0.f ? bia_ : LEAKY * bia_;
            sgb = sgb > 0.f ? sgb : LEAKY * sgb;
            bib = bib > 0.f ? bib : LEAKY * bib;
            float outa = sga + bia_;
            float outb = sgb + bib;

            float p = outa * outa + outb * outb;
            #pragma unroll
            for (int o = JW / 2; o > 0; o >>= 1)
                p += __shfl_xor_sync(0xffffffffu, p, o);
            float inv = 1.f / fmaxf(sqrtf(p), 1e-12f);

            int row = base + rg * R + rr;
            if (row < N_NODES) {
                ego_out[(size_t)row * DOUT + j]      = outa;
                ego_out[(size_t)row * DOUT + j + JW] = outb;
                all_emb[(size_t)row * OUT_COLS + col_off + j]      = outa * inv;
                all_emb[(size_t)row * OUT_COLS + col_off + j + JW] = outb * inv;
            }
        }
        __syncthreads();   // protect sx reuse
    }
}

// ---------------- final gather: (u_e, pos_i_e, neg_i_e) ----------------------
__global__ void gather_kernel(const int* __restrict__ users,
                              const int* __restrict__ pos,
                              const int* __restrict__ neg,
                              const float4* __restrict__ u4,
                              const float4* __restrict__ e4,
                              float4* __restrict__ out4) {
    int gid = blockIdx.x * blockDim.x + threadIdx.x;
    if (gid >= 3 * BATCH * 44) return;
    int idx   = gid / 44;
    int c     = gid - idx * 44;
    int which = idx / BATCH;
    int b     = idx - which * BATCH;
    int row = (which == 0) ? users[b]
            : (which == 1) ? (N_USERS + pos[b])
                           : (N_USERS + neg[b]);
    float4 v;
    if (c < 16) {
        v = (row < N_USERS) ? u4[(size_t)row * 16 + c]
                            : e4[(size_t)(row - N_USERS) * 16 + c];
    } else {
        v = g_all4[(size_t)row * 44 + c];
    }
    out4[gid] = v;
}

// -----------------------------------------------------------------------------
extern "C" void kernel_launch(void* const* d_in, const int* in_sizes, int n_in,
                              void* d_out, int out_size) {
    const int*   users = (const int*)  d_in[0];
    const int*   pos   = (const int*)  d_in[1];
    const int*   neg   = (const int*)  d_in[2];
    const int*   all_h = (const int*)  d_in[3];
    const int*   all_t = (const int*)  d_in[4];
    const float* Aval  = (const float*)d_in[5];
    const float* u_emb = (const float*)d_in[6];
    const float* e_emb = (const float*)d_in[7];
    const float* Wg0 = (const float*)d_in[8];
    const float* bg0 = (const float*)d_in[9];
    const float* Wb0 = (const float*)d_in[10];
    const float* bb0 = (const float*)d_in[11];
    const float* Wg1 = (const float*)d_in[12];
    const float* bg1 = (const float*)d_in[13];
    const float* Wb1 = (const float*)d_in[14];
    const float* bb1 = (const float*)d_in[15];
    const float* Wg2 = (const float*)d_in[16];
    const float* bg2 = (const float*)d_in[17];
    const float* Wb2 = (const float*)d_in[18];
    const float* bb2 = (const float*)d_in[19];

    void *pA, *pB, *pX, *pAll, *pCur;
    cudaGetSymbolAddress(&pA,   g_egoA4);
    cudaGetSymbolAddress(&pB,   g_egoB4);
    cudaGetSymbolAddress(&pX,   g_x4);
    cudaGetSymbolAddress(&pAll, g_all4);
    cudaGetSymbolAddress(&pCur, g_cursor);
    float* egoA = (float*)pA;
    float* egoB = (float*)pB;
    float4* x4  = (float4*)pX;
    float* all  = (float*)pAll;

    const int TB = 256;
    const int GEMM_GRID = 148 * 8;
    const int AGG_GRID  = (N_NODES * 32 + TB - 1) / TB;

    // dynamic smem sizes (float4 units -> bytes)
    const int smem0 = (2 * 32 * 33 + 32 * 32 + 32) * 16;   // 64->64
    const int smem1 = (2 * 16 * 33 + 64 * 32 + 16) * 16;   // 64->32
    const int smem2 = (2 * 8  * 17 + 128 * 16 + 8) * 16;   // 32->16
    cudaFuncSetAttribute(gemm_kernel<64, 64, 4>,
                         cudaFuncAttributeMaxDynamicSharedMemorySize, smem0);
    cudaFuncSetAttribute(gemm_kernel<64, 32, 4>,
                         cudaFuncAttributeMaxDynamicSharedMemorySize, smem1);
    cudaFuncSetAttribute(gemm_kernel<32, 16, 4>,
                         cudaFuncAttributeMaxDynamicSharedMemorySize, smem2);

    // ---- CSR build (once, reused by all 3 layers) ----
    cudaMemsetAsync(pCur, 0, N_NODES * sizeof(int));
    hist_kernel<<<(N_EDGES + TB - 1) / TB, TB>>>(all_h);
    scan_pass1<<<SCAN_BLOCKS, 256>>>();
    scan_pass2<<<1, 256>>>();
    scan_pass3<<<SCAN_BLOCKS, 256>>>();
    fill_kernel<<<(N_EDGES + TB - 1) / TB, TB>>>(all_h, all_t, Aval);

    // ---- layer 0: 64 -> 64 (embeds -> egoB), norm to cols [64,128) ----
    agg64_split_kernel<<<AGG_GRID, TB>>>(
        (const float2*)u_emb, (const float2*)e_emb, x4);
    gemm_kernel<64, 64, 4><<<GEMM_GRID, TB, smem0>>>(
        x4, egoB, Wg0, bg0, Wb0, bb0, all, 64);

    // ---- layer 1: 64 -> 32 (egoB -> egoA), norm to cols [128,160) ----
    agg64_kernel<<<AGG_GRID, TB>>>((const float2*)egoB, x4);
    gemm_kernel<64, 32, 4><<<GEMM_GRID, TB, smem1>>>(
        x4, egoA, Wg1, bg1, Wb1, bb1, all, 128);

    // ---- layer 2: 32 -> 16 (egoA -> egoB), norm to cols [160,176) ----
    agg32_kernel<<<AGG_GRID, TB>>>((const float*)egoA, (float2*)x4);
    gemm_kernel<32, 16, 4><<<GEMM_GRID, TB, smem2>>>(
        x4, egoB, Wg2, bg2, Wb2, bb2, all, 160);

    // ---- batched gather ----
    gather_kernel<<<(3 * BATCH * 44 + TB - 1) / TB, TB>>>(
        users, pos, neg, (const float4*)u_emb, (const float4*)e_emb,
        (float4*)d_out);
}